// round 5
// baseline (speedup 1.0000x reference)
#include <cuda_runtime.h>
#include <cstdint>

#define TWO_PI_F 6.283185307179586f
#define S_TOTAL 1024
#define Dm 96
#define Din 64
#define NBg 8
#define WELEM (Dm * Dm)          // 9216
#define CHUNK 128

typedef unsigned long long u64;

// Scratch: per-position weight matrices, layout W[s][j][i] (i contiguous)
__device__ float g_W1[(size_t)S_TOTAL * WELEM];
__device__ float g_W2[(size_t)S_TOTAL * WELEM];
// Pre-transposed static matrices: [k][i], i contiguous
__device__ float gM1T[Din * Dm];
__device__ float gWrT[Din * Dm];
__device__ float gM2T[Dm * Dm];

__device__ __forceinline__ u64 f2fma(u64 a, u64 b, u64 c) {
    u64 d; asm("fma.rn.f32x2 %0, %1, %2, %3;" : "=l"(d) : "l"(a), "l"(b), "l"(c)); return d;
}
__device__ __forceinline__ u64 f2add(u64 a, u64 b) {
    u64 d; asm("add.rn.f32x2 %0, %1, %2;" : "=l"(d) : "l"(a), "l"(b)); return d;
}
__device__ __forceinline__ u64 pk2(float lo, float hi) {
    u64 r; asm("mov.b64 %0, {%1, %2};" : "=l"(r) : "f"(lo), "f"(hi)); return r;
}
__device__ __forceinline__ void up2(u64 v, float& lo, float& hi) {
    asm("mov.b64 {%0, %1}, %2;" : "=f"(lo), "=f"(hi) : "l"(v));
}

__device__ __forceinline__ float warp_sum(float v) {
    v += __shfl_xor_sync(0xffffffffu, v, 16);
    v += __shfl_xor_sync(0xffffffffu, v, 8);
    v += __shfl_xor_sync(0xffffffffu, v, 4);
    v += __shfl_xor_sync(0xffffffffu, v, 2);
    v += __shfl_xor_sync(0xffffffffu, v, 1);
    return v;
}

// ---------------------------------------------------------------------------
// Kernel 1: W[s,i,j] = sum_g P[i,j,g]*cos(2*pi*s/T), T=(i*96+j)*8+g+2 via
// Chebyshev recurrence, packed f32x2 math. Also transposes M1/Wres1/M2.
// ---------------------------------------------------------------------------
__global__ void __launch_bounds__(256) precompute_W(
    const float* __restrict__ P1, const float* __restrict__ P2,
    const float* __restrict__ M1, const float* __restrict__ Wr,
    const float* __restrict__ M2)
{
    const int e = blockIdx.x * 256 + threadIdx.x;       // 0..9215

    if (blockIdx.y == 0 && blockIdx.z == 0) {
        if (e < Dm * Din) {
            int i = e / Din, k = e - i * Din;
            gM1T[k * Dm + i] = M1[e];
            gWrT[k * Dm + i] = Wr[e];
        }
        if (e < Dm * Dm) {
            int i = e / Dm, k = e - i * Dm;
            gM2T[k * Dm + i] = M2[e];
        }
    }

    const float* __restrict__ P = blockIdx.z ? P2 : P1;
    float* __restrict__ Wg = blockIdx.z ? g_W2 : g_W1;
    const int i = e % Dm;
    const int j = e / Dm;
    const int base = (i * Dm + j) * NBg;
    const int s0 = blockIdx.y * CHUNK;

    float c[NBg], q[NBg], a2[NBg];
#pragma unroll
    for (int g = 0; g < NBg; g++) {
        float T = (float)(base + g + 2);
        float invT = 1.0f / T;
        a2[g] = 2.0f * cosf(TWO_PI_F * invT);
        c[g]  = cosf(TWO_PI_F * (fmodf((float)s0, T) * invT));
        q[g]  = cosf(TWO_PI_F * (fmodf((float)(s0 - 1), T) * invT));
    }

    u64 C[4], N[4], A[4], Pp[4];
#pragma unroll
    for (int h = 0; h < 4; h++) {
        C[h]  = pk2(c[2*h], c[2*h+1]);
        N[h]  = pk2(-q[2*h], -q[2*h+1]);
        A[h]  = pk2(a2[2*h], a2[2*h+1]);
        Pp[h] = pk2(P[base + 2*h], P[base + 2*h + 1]);
    }

    float* __restrict__ outp = Wg + (size_t)s0 * WELEM + e;
#pragma unroll 4
    for (int s = 0; s < CHUNK; s++) {
        u64 acc0 = f2fma(Pp[0], C[0], f2fma(Pp[1], C[1], 0ULL));
        u64 acc1 = f2fma(Pp[2], C[2], f2fma(Pp[3], C[3], 0ULL));
        u64 t = f2add(acc0, acc1);
        float lo, hi; up2(t, lo, hi);
        outp[(size_t)s * WELEM] = lo + hi;
#pragma unroll
        for (int h = 0; h < 4; h++) {
            u64 cn = f2fma(A[h], C[h], N[h]);          // c_{s+1} = a2*c - c_{s-1}
            N[h] = C[h] ^ 0x8000000080000000ULL;       // -c_s   (ALU pipe)
            C[h] = cn;
        }
    }
}

// ---------------------------------------------------------------------------
// Kernel 2: fully fused. ONE WARP per position s. Lane owns i in
// {lane, lane+32, lane+64}; all 8 batches carried as 4 f32x2 pairs ->
// 12 packed accumulators. Each W element is loaded once chip-wide and
// feeds 8 FMAs (12 f32x2 FMA per 3 LDG). 256 blocks x 128 thr.
// ---------------------------------------------------------------------------
__global__ void __launch_bounds__(128) layers_kernel(
    const float* __restrict__ seq,
    const float* __restrict__ g1v, const float* __restrict__ b1v,
    const float* __restrict__ g2v, const float* __restrict__ b2v,
    float* __restrict__ out)
{
    __shared__ __align__(16) float xb_s[4][Din * 8];   // [k][b]
    __shared__ __align__(16) float buf_s[4][Dm * 8];   // [j][b], reused 3x

    const int w = threadIdx.x >> 5;
    const int lane = threadIdx.x & 31;
    const int s = blockIdx.x * 4 + w;
    float* xb = xb_s[w];
    float* buf = buf_s[w];

    const int i0 = lane, i1 = lane + 32, i2 = lane + 64;

    // ---- stage x[k][b] ----
#pragma unroll
    for (int b = 0; b < 8; b++) {
        xb[i0 * 8 + b] = seq[((size_t)b * S_TOTAL + s) * Din + i0];
        xb[i1 * 8 + b] = seq[((size_t)b * S_TOTAL + s) * Din + i1];
    }
    __syncwarp();

    const float G1[3] = {g1v[i0], g1v[i1], g1v[i2]};
    const float B1[3] = {b1v[i0], b1v[i1], b1v[i2]};
    const float G2[3] = {g2v[i0], g2v[i1], g2v[i2]};
    const float B2[3] = {b2v[i0], b2v[i1], b2v[i2]};

    // ---- phase 1: xt = M1 x, res = Wres1 x  (12 packed accs each) ----
    u64 xta[12], rsa[12];
#pragma unroll
    for (int q = 0; q < 12; q++) { xta[q] = 0ULL; rsa[q] = 0ULL; }
#pragma unroll 4
    for (int k = 0; k < Din; k++) {
        const float* mr = gM1T + k * Dm;
        const float* rr = gWrT + k * Dm;
        float m0 = mr[i0], m1 = mr[i1], m2 = mr[i2];
        float r0 = rr[i0], r1 = rr[i1], r2 = rr[i2];
        u64 M0 = pk2(m0, m0), M1p = pk2(m1, m1), M2p = pk2(m2, m2);
        u64 R0 = pk2(r0, r0), R1p = pk2(r1, r1), R2p = pk2(r2, r2);
        const u64* xq = (const u64*)(xb + k * 8);
#pragma unroll
        for (int p = 0; p < 4; p++) {
            u64 xp = xq[p];
            xta[p*3+0] = f2fma(M0,  xp, xta[p*3+0]);
            xta[p*3+1] = f2fma(M1p, xp, xta[p*3+1]);
            xta[p*3+2] = f2fma(M2p, xp, xta[p*3+2]);
            rsa[p*3+0] = f2fma(R0,  xp, rsa[p*3+0]);
            rsa[p*3+1] = f2fma(R1p, xp, rsa[p*3+1]);
            rsa[p*3+2] = f2fma(R2p, xp, rsa[p*3+2]);
        }
    }

    // ---- LN1 -> buf[j][b] ----
    {
        float xt[8][3], xn[8][3];
#pragma unroll
        for (int p = 0; p < 4; p++)
#pragma unroll
            for (int t = 0; t < 3; t++)
                up2(xta[p*3+t], xt[2*p][t], xt[2*p+1][t]);
#pragma unroll
        for (int b = 0; b < 8; b++) {
            float mu = warp_sum(xt[b][0] + xt[b][1] + xt[b][2]) * (1.0f/96.0f);
            float d0 = xt[b][0]-mu, d1 = xt[b][1]-mu, d2 = xt[b][2]-mu;
            float var = warp_sum(d0*d0 + d1*d1 + d2*d2) * (1.0f/96.0f);
            float rq = rsqrtf(var + 1e-5f);
            xn[b][0] = fmaf(d0*rq, G1[0], B1[0]);
            xn[b][1] = fmaf(d1*rq, G1[1], B1[1]);
            xn[b][2] = fmaf(d2*rq, G1[2], B1[2]);
        }
#pragma unroll
        for (int t = 0; t < 3; t++) {
            int jj = lane + 32*t;
            *(float4*)(buf + jj*8)     = make_float4(xn[0][t], xn[1][t], xn[2][t], xn[3][t]);
            *(float4*)(buf + jj*8 + 4) = make_float4(xn[4][t], xn[5][t], xn[6][t], xn[7][t]);
        }
    }
    __syncwarp();

    // ---- x1 = W1[s] @ xn1 + res ----
    u64 x1a[12];
#pragma unroll
    for (int q = 0; q < 12; q++) x1a[q] = rsa[q];
    {
        const float* __restrict__ Wr = g_W1 + (size_t)s * WELEM;
#pragma unroll 4
        for (int j = 0; j < Dm; j++) {
            float w0 = Wr[j*Dm + i0], w1 = Wr[j*Dm + i1], w2 = Wr[j*Dm + i2];
            u64 W0 = pk2(w0, w0), W1p = pk2(w1, w1), W2p = pk2(w2, w2);
            const u64* xq = (const u64*)(buf + j * 8);
#pragma unroll
            for (int p = 0; p < 4; p++) {
                u64 xp = xq[p];
                x1a[p*3+0] = f2fma(W0,  xp, x1a[p*3+0]);
                x1a[p*3+1] = f2fma(W1p, xp, x1a[p*3+1]);
                x1a[p*3+2] = f2fma(W2p, xp, x1a[p*3+2]);
            }
        }
    }
    __syncwarp();   // xn1 reads done before overwrite

    // ---- store x1 -> buf ----
    {
        float x1[8][3];
#pragma unroll
        for (int p = 0; p < 4; p++)
#pragma unroll
            for (int t = 0; t < 3; t++)
                up2(x1a[p*3+t], x1[2*p][t], x1[2*p+1][t]);
#pragma unroll
        for (int t = 0; t < 3; t++) {
            int jj = lane + 32*t;
            *(float4*)(buf + jj*8)     = make_float4(x1[0][t], x1[1][t], x1[2][t], x1[3][t]);
            *(float4*)(buf + jj*8 + 4) = make_float4(x1[4][t], x1[5][t], x1[6][t], x1[7][t]);
        }
    }
    __syncwarp();

    // ---- xt2 = M2 x1 ----
    u64 t2a[12];
#pragma unroll
    for (int q = 0; q < 12; q++) t2a[q] = 0ULL;
#pragma unroll 4
    for (int k = 0; k < Dm; k++) {
        const float* mr = gM2T + k * Dm;
        float m0 = mr[i0], m1 = mr[i1], m2 = mr[i2];
        u64 M0 = pk2(m0, m0), M1p = pk2(m1, m1), M2p = pk2(m2, m2);
        const u64* xq = (const u64*)(buf + k * 8);
#pragma unroll
        for (int p = 0; p < 4; p++) {
            u64 xp = xq[p];
            t2a[p*3+0] = f2fma(M0,  xp, t2a[p*3+0]);
            t2a[p*3+1] = f2fma(M1p, xp, t2a[p*3+1]);
            t2a[p*3+2] = f2fma(M2p, xp, t2a[p*3+2]);
        }
    }
    __syncwarp();   // x1 reads done before overwrite

    // ---- LN2 -> buf[j][b] ----
    {
        float xt[8][3], xn[8][3];
#pragma unroll
        for (int p = 0; p < 4; p++)
#pragma unroll
            for (int t = 0; t < 3; t++)
                up2(t2a[p*3+t], xt[2*p][t], xt[2*p+1][t]);
#pragma unroll
        for (int b = 0; b < 8; b++) {
            float mu = warp_sum(xt[b][0] + xt[b][1] + xt[b][2]) * (1.0f/96.0f);
            float d0 = xt[b][0]-mu, d1 = xt[b][1]-mu, d2 = xt[b][2]-mu;
            float var = warp_sum(d0*d0 + d1*d1 + d2*d2) * (1.0f/96.0f);
            float rq = rsqrtf(var + 1e-5f);
            xn[b][0] = fmaf(d0*rq, G2[0], B2[0]);
            xn[b][1] = fmaf(d1*rq, G2[1], B2[1]);
            xn[b][2] = fmaf(d2*rq, G2[2], B2[2]);
        }
#pragma unroll
        for (int t = 0; t < 3; t++) {
            int jj = lane + 32*t;
            *(float4*)(buf + jj*8)     = make_float4(xn[0][t], xn[1][t], xn[2][t], xn[3][t]);
            *(float4*)(buf + jj*8 + 4) = make_float4(xn[4][t], xn[5][t], xn[6][t], xn[7][t]);
        }
    }
    __syncwarp();

    // ---- out = W2[s] @ xn2 + x1 ----
    u64 oa[12];
#pragma unroll
    for (int q = 0; q < 12; q++) oa[q] = x1a[q];
    {
        const float* __restrict__ Wr = g_W2 + (size_t)s * WELEM;
#pragma unroll 4
        for (int j = 0; j < Dm; j++) {
            float w0 = Wr[j*Dm + i0], w1 = Wr[j*Dm + i1], w2 = Wr[j*Dm + i2];
            u64 W0 = pk2(w0, w0), W1p = pk2(w1, w1), W2p = pk2(w2, w2);
            const u64* xq = (const u64*)(buf + j * 8);
#pragma unroll
            for (int p = 0; p < 4; p++) {
                u64 xp = xq[p];
                oa[p*3+0] = f2fma(W0,  xp, oa[p*3+0]);
                oa[p*3+1] = f2fma(W1p, xp, oa[p*3+1]);
                oa[p*3+2] = f2fma(W2p, xp, oa[p*3+2]);
            }
        }
    }

    // ---- epilogue: unpack + store ----
    {
        float o[8][3];
#pragma unroll
        for (int p = 0; p < 4; p++)
#pragma unroll
            for (int t = 0; t < 3; t++)
                up2(oa[p*3+t], o[2*p][t], o[2*p+1][t]);
#pragma unroll
        for (int b = 0; b < 8; b++) {
            float* op = out + ((size_t)b * S_TOTAL + s) * Dm;
            op[i0] = o[b][0];
            op[i1] = o[b][1];
            op[i2] = o[b][2];
        }
    }
}

extern "C" void kernel_launch(void* const* d_in, const int* in_sizes, int n_in,
                              void* d_out, int out_size) {
    const float* seq = (const float*)d_in[0];
    const float* M1  = (const float*)d_in[1];
    const float* P1  = (const float*)d_in[2];
    const float* Wr1 = (const float*)d_in[3];
    const float* g1  = (const float*)d_in[4];
    const float* b1  = (const float*)d_in[5];
    const float* M2  = (const float*)d_in[6];
    const float* P2  = (const float*)d_in[7];
    const float* g2  = (const float*)d_in[8];
    const float* b2  = (const float*)d_in[9];
    float* out = (float*)d_out;

    precompute_W<<<dim3(WELEM / 256, S_TOTAL / CHUNK, 2), 256>>>(P1, P2, M1, Wr1, M2);
    layers_kernel<<<S_TOTAL / 4, 128>>>(seq, g1, b1, g2, b2, out);
}

// round 8
// speedup vs baseline: 1.7305x; 1.7305x over previous
#include <cuda_runtime.h>
#include <cstdint>

#define TWO_PI_F 6.283185307179586f
#define S_TOTAL 1024
#define Dm 96
#define Din 64
#define NBg 8
#define WELEM (Dm * Dm)          // 9216
#define CHUNK 128

typedef unsigned long long u64;

// Scratch: per-position weight matrices, layout W[s][j][i] (i contiguous)
__device__ float g_W1[(size_t)S_TOTAL * WELEM];
__device__ float g_W2[(size_t)S_TOTAL * WELEM];
// Pre-transposed static matrices: [k][i], i contiguous
__device__ float gM1T[Din * Dm];
__device__ float gWrT[Din * Dm];
__device__ float gM2T[Dm * Dm];

__device__ __forceinline__ u64 f2fma(u64 a, u64 b, u64 c) {
    u64 d; asm("fma.rn.f32x2 %0, %1, %2, %3;" : "=l"(d) : "l"(a), "l"(b), "l"(c)); return d;
}
__device__ __forceinline__ u64 f2add(u64 a, u64 b) {
    u64 d; asm("add.rn.f32x2 %0, %1, %2;" : "=l"(d) : "l"(a), "l"(b)); return d;
}
__device__ __forceinline__ u64 pk2(float lo, float hi) {
    u64 r; asm("mov.b64 %0, {%1, %2};" : "=l"(r) : "f"(lo), "f"(hi)); return r;
}
__device__ __forceinline__ void up2(u64 v, float& lo, float& hi) {
    asm("mov.b64 {%0, %1}, %2;" : "=f"(lo), "=f"(hi) : "l"(v));
}

__device__ __forceinline__ float warp_sum(float v) {
    v += __shfl_xor_sync(0xffffffffu, v, 16);
    v += __shfl_xor_sync(0xffffffffu, v, 8);
    v += __shfl_xor_sync(0xffffffffu, v, 4);
    v += __shfl_xor_sync(0xffffffffu, v, 2);
    v += __shfl_xor_sync(0xffffffffu, v, 1);
    return v;
}

// ---------------------------------------------------------------------------
// Kernel 1: W[s,i,j] = sum_g P[i,j,g]*cos(2*pi*s/T), T=(i*96+j)*8+g+2 via
// Chebyshev recurrence, packed f32x2 math. Also transposes M1/Wres1/M2.
// ---------------------------------------------------------------------------
__global__ void __launch_bounds__(256) precompute_W(
    const float* __restrict__ P1, const float* __restrict__ P2,
    const float* __restrict__ M1, const float* __restrict__ Wr,
    const float* __restrict__ M2)
{
    const int e = blockIdx.x * 256 + threadIdx.x;       // 0..9215

    if (blockIdx.y == 0 && blockIdx.z == 0) {
        if (e < Dm * Din) {
            int i = e / Din, k = e - i * Din;
            gM1T[k * Dm + i] = M1[e];
            gWrT[k * Dm + i] = Wr[e];
        }
        if (e < Dm * Dm) {
            int i = e / Dm, k = e - i * Dm;
            gM2T[k * Dm + i] = M2[e];
        }
    }

    const float* __restrict__ P = blockIdx.z ? P2 : P1;
    float* __restrict__ Wg = blockIdx.z ? g_W2 : g_W1;
    const int i = e % Dm;
    const int j = e / Dm;
    const int base = (i * Dm + j) * NBg;
    const int s0 = blockIdx.y * CHUNK;

    float c[NBg], q[NBg], a2[NBg];
#pragma unroll
    for (int g = 0; g < NBg; g++) {
        float T = (float)(base + g + 2);
        float invT = 1.0f / T;
        a2[g] = 2.0f * cosf(TWO_PI_F * invT);
        c[g]  = cosf(TWO_PI_F * (fmodf((float)s0, T) * invT));
        q[g]  = cosf(TWO_PI_F * (fmodf((float)(s0 - 1), T) * invT));
    }

    u64 C[4], N[4], A[4], Pp[4];
#pragma unroll
    for (int h = 0; h < 4; h++) {
        C[h]  = pk2(c[2*h], c[2*h+1]);
        N[h]  = pk2(-q[2*h], -q[2*h+1]);
        A[h]  = pk2(a2[2*h], a2[2*h+1]);
        Pp[h] = pk2(P[base + 2*h], P[base + 2*h + 1]);
    }

    float* __restrict__ outp = Wg + (size_t)s0 * WELEM + e;
#pragma unroll 4
    for (int s = 0; s < CHUNK; s++) {
        u64 acc0 = f2fma(Pp[0], C[0], f2fma(Pp[1], C[1], 0ULL));
        u64 acc1 = f2fma(Pp[2], C[2], f2fma(Pp[3], C[3], 0ULL));
        u64 t = f2add(acc0, acc1);
        float lo, hi; up2(t, lo, hi);
        outp[(size_t)s * WELEM] = lo + hi;
#pragma unroll
        for (int h = 0; h < 4; h++) {
            u64 cn = f2fma(A[h], C[h], N[h]);          // c_{s+1} = a2*c - c_{s-1}
            N[h] = C[h] ^ 0x8000000080000000ULL;       // -c_s   (ALU pipe)
            C[h] = cn;
        }
    }
}

// ---------------------------------------------------------------------------
// Kernel 2: fully fused. TWO WARPS per position s (batch halves of 4).
// Lane owns i in {lane, lane+32, lane+64}; 4 batches as 2 f32x2 pairs ->
// 6 packed accumulators per quantity. Fully warp-independent (LN sums are
// over i = intra-warp). 256 blocks x 256 thr = 2048 warps, 4 positions/block.
// ---------------------------------------------------------------------------
__global__ void __launch_bounds__(256) layers_kernel(
    const float* __restrict__ seq,
    const float* __restrict__ g1v, const float* __restrict__ b1v,
    const float* __restrict__ g2v, const float* __restrict__ b2v,
    float* __restrict__ out)
{
    __shared__ __align__(16) float xb_s[8][Din * 4];   // per-warp [k][4b]
    __shared__ __align__(16) float buf_s[8][Dm * 4];   // per-warp [j][4b]

    const int w = threadIdx.x >> 5;
    const int lane = threadIdx.x & 31;
    const int s = blockIdx.x * 4 + (w >> 1);
    const int b0 = (w & 1) * 4;                        // batches b0..b0+3
    float* xb = xb_s[w];
    float* buf = buf_s[w];

    const int i0 = lane, i1 = lane + 32, i2 = lane + 64;

    // ---- stage x[k][4] for this warp's 4 batches ----
#pragma unroll
    for (int b = 0; b < 4; b++) {
        xb[i0 * 4 + b] = seq[((size_t)(b0 + b) * S_TOTAL + s) * Din + i0];
        xb[i1 * 4 + b] = seq[((size_t)(b0 + b) * S_TOTAL + s) * Din + i1];
    }
    __syncwarp();

    const float G1[3] = {g1v[i0], g1v[i1], g1v[i2]};
    const float B1[3] = {b1v[i0], b1v[i1], b1v[i2]};
    const float G2[3] = {g2v[i0], g2v[i1], g2v[i2]};
    const float B2[3] = {b2v[i0], b2v[i1], b2v[i2]};

    // ---- phase 1: xt = M1 x, res = Wres1 x  (6 packed accs each) ----
    u64 xta[6], rsa[6];
#pragma unroll
    for (int q = 0; q < 6; q++) { xta[q] = 0ULL; rsa[q] = 0ULL; }
#pragma unroll 4
    for (int k = 0; k < Din; k++) {
        const float* mr = gM1T + k * Dm;
        const float* rr = gWrT + k * Dm;
        float m0 = mr[i0], m1 = mr[i1], m2 = mr[i2];
        float r0 = rr[i0], r1 = rr[i1], r2 = rr[i2];
        u64 M0 = pk2(m0, m0), M1p = pk2(m1, m1), M2p = pk2(m2, m2);
        u64 R0 = pk2(r0, r0), R1p = pk2(r1, r1), R2p = pk2(r2, r2);
        const u64* xq = (const u64*)(xb + k * 4);
#pragma unroll
        for (int p = 0; p < 2; p++) {
            u64 xp = xq[p];
            xta[p*3+0] = f2fma(M0,  xp, xta[p*3+0]);
            xta[p*3+1] = f2fma(M1p, xp, xta[p*3+1]);
            xta[p*3+2] = f2fma(M2p, xp, xta[p*3+2]);
            rsa[p*3+0] = f2fma(R0,  xp, rsa[p*3+0]);
            rsa[p*3+1] = f2fma(R1p, xp, rsa[p*3+1]);
            rsa[p*3+2] = f2fma(R2p, xp, rsa[p*3+2]);
        }
    }

    // ---- LN1 -> buf[j][4] ----
    {
        float xt[4][3], xn[4][3];
#pragma unroll
        for (int p = 0; p < 2; p++)
#pragma unroll
            for (int t = 0; t < 3; t++)
                up2(xta[p*3+t], xt[2*p][t], xt[2*p+1][t]);
#pragma unroll
        for (int b = 0; b < 4; b++) {
            float mu = warp_sum(xt[b][0] + xt[b][1] + xt[b][2]) * (1.0f/96.0f);
            float d0 = xt[b][0]-mu, d1 = xt[b][1]-mu, d2 = xt[b][2]-mu;
            float var = warp_sum(d0*d0 + d1*d1 + d2*d2) * (1.0f/96.0f);
            float rq = rsqrtf(var + 1e-5f);
            xn[b][0] = fmaf(d0*rq, G1[0], B1[0]);
            xn[b][1] = fmaf(d1*rq, G1[1], B1[1]);
            xn[b][2] = fmaf(d2*rq, G1[2], B1[2]);
        }
#pragma unroll
        for (int t = 0; t < 3; t++) {
            int jj = lane + 32*t;
            *(float4*)(buf + jj*4) = make_float4(xn[0][t], xn[1][t], xn[2][t], xn[3][t]);
        }
    }
    __syncwarp();

    // ---- x1 = W1[s] @ xn1 + res ----
    u64 x1a[6];
#pragma unroll
    for (int q = 0; q < 6; q++) x1a[q] = rsa[q];
    {
        const float* __restrict__ Wr = g_W1 + (size_t)s * WELEM;
#pragma unroll 4
        for (int j = 0; j < Dm; j++) {
            float w0 = Wr[j*Dm + i0], w1 = Wr[j*Dm + i1], w2 = Wr[j*Dm + i2];
            u64 W0 = pk2(w0, w0), W1p = pk2(w1, w1), W2p = pk2(w2, w2);
            const u64* xq = (const u64*)(buf + j * 4);
#pragma unroll
            for (int p = 0; p < 2; p++) {
                u64 xp = xq[p];
                x1a[p*3+0] = f2fma(W0,  xp, x1a[p*3+0]);
                x1a[p*3+1] = f2fma(W1p, xp, x1a[p*3+1]);
                x1a[p*3+2] = f2fma(W2p, xp, x1a[p*3+2]);
            }
        }
    }
    __syncwarp();   // xn1 reads done before overwrite

    // ---- store x1 -> buf ----
    {
        float x1[4][3];
#pragma unroll
        for (int p = 0; p < 2; p++)
#pragma unroll
            for (int t = 0; t < 3; t++)
                up2(x1a[p*3+t], x1[2*p][t], x1[2*p+1][t]);
#pragma unroll
        for (int t = 0; t < 3; t++) {
            int jj = lane + 32*t;
            *(float4*)(buf + jj*4) = make_float4(x1[0][t], x1[1][t], x1[2][t], x1[3][t]);
        }
    }
    __syncwarp();

    // ---- xt2 = M2 x1 ----
    u64 t2a[6];
#pragma unroll
    for (int q = 0; q < 6; q++) t2a[q] = 0ULL;
#pragma unroll 4
    for (int k = 0; k < Dm; k++) {
        const float* mr = gM2T + k * Dm;
        float m0 = mr[i0], m1 = mr[i1], m2 = mr[i2];
        u64 M0 = pk2(m0, m0), M1p = pk2(m1, m1), M2p = pk2(m2, m2);
        const u64* xq = (const u64*)(buf + k * 4);
#pragma unroll
        for (int p = 0; p < 2; p++) {
            u64 xp = xq[p];
            t2a[p*3+0] = f2fma(M0,  xp, t2a[p*3+0]);
            t2a[p*3+1] = f2fma(M1p, xp, t2a[p*3+1]);
            t2a[p*3+2] = f2fma(M2p, xp, t2a[p*3+2]);
        }
    }
    __syncwarp();   // x1 reads done before overwrite

    // ---- LN2 -> buf[j][4] ----
    {
        float xt[4][3], xn[4][3];
#pragma unroll
        for (int p = 0; p < 2; p++)
#pragma unroll
            for (int t = 0; t < 3; t++)
                up2(t2a[p*3+t], xt[2*p][t], xt[2*p+1][t]);
#pragma unroll
        for (int b = 0; b < 4; b++) {
            float mu = warp_sum(xt[b][0] + xt[b][1] + xt[b][2]) * (1.0f/96.0f);
            float d0 = xt[b][0]-mu, d1 = xt[b][1]-mu, d2 = xt[b][2]-mu;
            float var = warp_sum(d0*d0 + d1*d1 + d2*d2) * (1.0f/96.0f);
            float rq = rsqrtf(var + 1e-5f);
            xn[b][0] = fmaf(d0*rq, G2[0], B2[0]);
            xn[b][1] = fmaf(d1*rq, G2[1], B2[1]);
            xn[b][2] = fmaf(d2*rq, G2[2], B2[2]);
        }
#pragma unroll
        for (int t = 0; t < 3; t++) {
            int jj = lane + 32*t;
            *(float4*)(buf + jj*4) = make_float4(xn[0][t], xn[1][t], xn[2][t], xn[3][t]);
        }
    }
    __syncwarp();

    // ---- out = W2[s] @ xn2 + x1 ----
    u64 oa[6];
#pragma unroll
    for (int q = 0; q < 6; q++) oa[q] = x1a[q];
    {
        const float* __restrict__ Wr = g_W2 + (size_t)s * WELEM;
#pragma unroll 4
        for (int j = 0; j < Dm; j++) {
            float w0 = Wr[j*Dm + i0], w1 = Wr[j*Dm + i1], w2 = Wr[j*Dm + i2];
            u64 W0 = pk2(w0, w0), W1p = pk2(w1, w1), W2p = pk2(w2, w2);
            const u64* xq = (const u64*)(buf + j * 4);
#pragma unroll
            for (int p = 0; p < 2; p++) {
                u64 xp = xq[p];
                oa[p*3+0] = f2fma(W0,  xp, oa[p*3+0]);
                oa[p*3+1] = f2fma(W1p, xp, oa[p*3+1]);
                oa[p*3+2] = f2fma(W2p, xp, oa[p*3+2]);
            }
        }
    }

    // ---- epilogue: unpack + store ----
    {
        float o[4][3];
#pragma unroll
        for (int p = 0; p < 2; p++)
#pragma unroll
            for (int t = 0; t < 3; t++)
                up2(oa[p*3+t], o[2*p][t], o[2*p+1][t]);
#pragma unroll
        for (int b = 0; b < 4; b++) {
            float* op = out + ((size_t)(b0 + b) * S_TOTAL + s) * Dm;
            op[i0] = o[b][0];
            op[i1] = o[b][1];
            op[i2] = o[b][2];
        }
    }
}

extern "C" void kernel_launch(void* const* d_in, const int* in_sizes, int n_in,
                              void* d_out, int out_size) {
    const float* seq = (const float*)d_in[0];
    const float* M1  = (const float*)d_in[1];
    const float* P1  = (const float*)d_in[2];
    const float* Wr1 = (const float*)d_in[3];
    const float* g1  = (const float*)d_in[4];
    const float* b1  = (const float*)d_in[5];
    const float* M2  = (const float*)d_in[6];
    const float* P2  = (const float*)d_in[7];
    const float* g2  = (const float*)d_in[8];
    const float* b2  = (const float*)d_in[9];
    float* out = (float*)d_out;

    precompute_W<<<dim3(WELEM / 256, S_TOTAL / CHUNK, 2), 256>>>(P1, P2, M1, Wr1, M2);
    layers_kernel<<<S_TOTAL / 4, 256>>>(seq, g1, b1, g2, b2, out);
}